// round 14
// baseline (speedup 1.0000x reference)
#include <cuda_runtime.h>
#include <cuda_fp16.h>
#include <cstdint>

#define THREADS    384
#define TM         96
#define F_DIM      128
#define K_NEIGH    16
#define O_DIM      128
#define KD         256
#define NEG_SLOPE  0.2f
#define LN_EPS     1e-5f
#define X_MAX_ROWS 131072

// smem offsets (bytes)
#define OFF_A      0          // A: 96 rows x 512B (fp16 K=256, XOR-swizzled) = 49152
#define OFF_W      49152      // W chunk: 128 rows x 256B (fp16 K=128, swizzled) = 32768
#define OFF_ADJ    81920      // 96*16 int = 6144
#define OFF_SUMS   88064      // 96 x {s1,s2} f32 = 768
#define OFF_INV    88832      // 96 f32 (+pad)
#define OFF_BIAS   89216      // 128 f32
#define OFF_GAM    89728
#define OFF_BET    90240
#define SMEM_BYTES 90752

__device__ __half g_Wh[O_DIM * KD];
__device__ __half g_Xh[X_MAX_ROWS * F_DIM];

__device__ __forceinline__ uint32_t smem_u32(const void* p) {
    uint32_t a;
    asm("{ .reg .u64 t; cvta.to.shared.u64 t, %1; cvt.u32.u64 %0, t; }" : "=r"(a) : "l"(p));
    return a;
}
__device__ __forceinline__ void ldsm4(uint32_t* r, uint32_t addr) {
    asm volatile("ldmatrix.sync.aligned.m8n8.x4.shared.b16 {%0,%1,%2,%3}, [%4];"
        : "=r"(r[0]), "=r"(r[1]), "=r"(r[2]), "=r"(r[3]) : "r"(addr));
}
__device__ __forceinline__ void mma_f16(float* c, const uint32_t* a, const uint32_t* b) {
    asm volatile("mma.sync.aligned.m16n8k16.row.col.f32.f16.f16.f32 "
        "{%0,%1,%2,%3}, {%4,%5,%6,%7}, {%8,%9}, {%0,%1,%2,%3};"
        : "+f"(c[0]), "+f"(c[1]), "+f"(c[2]), "+f"(c[3])
        : "r"(a[0]), "r"(a[1]), "r"(a[2]), "r"(a[3]), "r"(b[0]), "r"(b[1]));
}
__device__ __forceinline__ uint32_t pkh2(float a, float b) {
    __half2 t = __floats2half2_rn(a, b);
    return *reinterpret_cast<uint32_t*>(&t);
}

// ---------- prep: convert W and X to fp16, then trigger dependent launch ----------
__global__ void prep_kernel(const float* __restrict__ X,
                            const float* __restrict__ W, int n4) {
    int i = blockIdx.x * blockDim.x + threadIdx.x;
    if (i < O_DIM * KD) g_Wh[i] = __float2half_rn(W[i]);
    if (i < n4) {
        float4 v = ((const float4*)X)[i];
        ((uint2*)g_Xh)[i] = make_uint2(pkh2(v.x, v.y), pkh2(v.z, v.w));
    }
    cudaTriggerProgrammaticLaunchCompletion();
}

// ---------- main fused kernel (PDL secondary) ----------
__global__ void __launch_bounds__(THREADS, 2)
gnn_mma_kernel(const float* __restrict__ X,
               const int* __restrict__ adj,
               const float* __restrict__ bias,
               const float* __restrict__ gamma,
               const float* __restrict__ beta,
               float* __restrict__ out,
               int N)
{
    extern __shared__ __align__(16) char sp[];
    const uint32_t sbase = smem_u32(sp);

    int*   sAdj = (int*)(sp + OFF_ADJ);
    float* sInv = (float*)(sp + OFF_INV);
    float* sums = (float*)(sp + OFF_SUMS);
    float* sB   = (float*)(sp + OFF_BIAS);
    float* sG   = (float*)(sp + OFF_GAM);
    float* sBe  = (float*)(sp + OFF_BET);

    const int tid  = threadIdx.x;
    const int lane = tid & 31;
    const int warp = tid >> 5;               // 12 warps
    const int wm   = warp >> 1;              // 6 in M (16 rows each)
    const int wn   = warp & 1;               // 2 in N (64 cols each)
    const int nodeBase = blockIdx.x * TM;
    const uint4* Xh4 = (const uint4*)g_Xh;   // 16B groups; 16 per row

    // ======== pre-dependency phase (does NOT touch g_Wh / g_Xh) ========
    if (tid < 128) { sB[tid] = bias[tid]; sG[tid] = gamma[tid]; sBe[tid] = beta[tid]; }

    // per-warp: adjacency (8 rows) + ballot count -> inv
    #pragma unroll
    for (int q = 0; q < 4; q++) {
        int idx = q * 32 + lane;                       // 0..127
        int r = warp * 8 + (idx >> 4);
        int node = nodeBase + r;
        int a = -1;
        if (node < N) a = adj[node * K_NEIGH + (idx & 15)];
        sAdj[warp * 128 + idx] = a;
        uint32_t m = __ballot_sync(0xFFFFFFFFu, a >= 0);
        if (lane == 0) {
            int c = __popc(m & 0xFFFFu);
            sInv[warp * 8 + 2 * q] = 1.0f / (float)(c > 1 ? c : 1);
        } else if (lane == 16) {
            int c = __popc(m >> 16);
            sInv[warp * 8 + 2 * q + 1] = 1.0f / (float)(c > 1 ? c : 1);
        }
    }
    // per-warp: self features from fp32 X (convert here; independent of prep)
    #pragma unroll
    for (int q = 0; q < 4; q++) {
        int idx = q * 32 + lane;
        int r = warp * 8 + (idx >> 4);
        int u = idx & 15;                              // 16B fp16 unit = 8 floats
        uint4 pk = make_uint4(0u, 0u, 0u, 0u);
        int node = nodeBase + r;
        if (node < N) {
            const float4* xr = (const float4*)(X + (size_t)node * F_DIM + u * 8);
            float4 x0 = xr[0], x1 = xr[1];
            pk = make_uint4(pkh2(x0.x, x0.y), pkh2(x0.z, x0.w),
                            pkh2(x1.x, x1.y), pkh2(x1.z, x1.w));
        }
        *(uint4*)(sp + OFF_A + r * 512 + (((u) ^ (r & 7)) << 4)) = pk;
    }

    // ======== wait for prep's g_Wh / g_Xh ========
    cudaGridDependencySynchronize();

    // stage W chunk 0 (block-stride; latency hides behind gather; barrier 1 covers)
    for (int idx = tid; idx < 2048; idx += THREADS) {
        int o = idx >> 4, u = idx & 15;
        *(uint4*)(sp + OFF_W + o * 256 + (((u) ^ (o & 7)) << 4)) =
            *(const uint4*)(g_Wh + o * KD + u * 8);
    }
    __syncwarp();

    // per-warp gather: pair-row, half-warp covers one 256B row (4 iterations)
    {
        const int u = lane & 15;
        #pragma unroll 1
        for (int p = 0; p < 4; p++) {
            int r = warp * 8 + 2 * p + (lane >> 4);
            const int* arow = sAdj + r * 16;
            float a0=0.f,a1=0.f,a2=0.f,a3=0.f,a4=0.f,a5=0.f,a6=0.f,a7=0.f;
            #pragma unroll
            for (int k = 0; k < K_NEIGH; k++) {
                int j = arow[k];
                if (j >= 0) {
                    uint4 v = Xh4[j * 16 + u];
                    float2 f;
                    f = __half22float2(*(__half2*)&v.x); a0 += f.x; a1 += f.y;
                    f = __half22float2(*(__half2*)&v.y); a2 += f.x; a3 += f.y;
                    f = __half22float2(*(__half2*)&v.z); a4 += f.x; a5 += f.y;
                    f = __half22float2(*(__half2*)&v.w); a6 += f.x; a7 += f.y;
                }
            }
            float inv = sInv[r];
            uint32_t un = 16u + (uint32_t)u;
            *(uint4*)(sp + OFF_A + r * 512 + ((un ^ (uint32_t)(r & 7)) << 4)) = make_uint4(
                pkh2(a0 * inv, a1 * inv), pkh2(a2 * inv, a3 * inv),
                pkh2(a4 * inv, a5 * inv), pkh2(a6 * inv, a7 * inv));
        }
    }

    float acc[8][4];
    #pragma unroll
    for (int nt = 0; nt < 8; nt++)
        #pragma unroll
        for (int j = 0; j < 4; j++) acc[nt][j] = 0.f;

    const int aRow = wm * 16 + (lane & 15);
    const int aSel = lane >> 4;
    const int bN   = wn * 64 + ((lane >> 4) << 3) + (lane & 7);
    const int bSel = (lane >> 3) & 1;

    __syncthreads();   // barrier 1: A + W0 ready

    #pragma unroll 1
    for (int chunk = 0; chunk < 2; chunk++) {
        if (chunk == 1) {
            for (int idx = tid; idx < 2048; idx += THREADS) {
                int o = idx >> 4, u = idx & 15;
                *(uint4*)(sp + OFF_W + o * 256 + (((u) ^ (o & 7)) << 4)) =
                    *(const uint4*)(g_Wh + o * KD + 128 + u * 8);
            }
            if (tid < 192) sums[tid] = 0.f;
            __syncthreads();   // barrier 3: W1 + sums ready
        }
        #pragma unroll
        for (int s = 0; s < 8; s++) {
            uint32_t a[4], bf[16];
            {
                uint32_t ku = (uint32_t)(chunk * 16 + s * 2 + aSel);
                ldsm4(a, sbase + OFF_A + (uint32_t)aRow * 512u
                         + ((ku ^ (uint32_t)(aRow & 7)) << 4));
            }
            #pragma unroll
            for (int q = 0; q < 4; q++) {
                int n = bN + q * 16;
                uint32_t ku = (uint32_t)(s * 2 + bSel);
                ldsm4(bf + q * 4, sbase + OFF_W + (uint32_t)n * 256u
                                  + ((ku ^ (uint32_t)(n & 7)) << 4));
            }
            #pragma unroll
            for (int nt = 0; nt < 8; nt++)
                mma_f16(acc[nt], a, bf + nt * 2);
        }
        if (chunk == 0) __syncthreads();   // barrier 2: GEMM c0 reads done before W restage
    }

    // ---- epilogue: bias + per-row sums (quad shfl + smem atomics) ----
    {
        float s1a = 0.f, s2a = 0.f, s1b = 0.f, s2b = 0.f;
        #pragma unroll
        for (int nt = 0; nt < 8; nt++) {
            int col = wn * 64 + nt * 8 + 2 * (lane & 3);
            float b0 = sB[col], b1 = sB[col + 1];
            acc[nt][0] += b0; acc[nt][1] += b1;
            acc[nt][2] += b0; acc[nt][3] += b1;
            s1a += acc[nt][0] + acc[nt][1];
            s2a += acc[nt][0] * acc[nt][0] + acc[nt][1] * acc[nt][1];
            s1b += acc[nt][2] + acc[nt][3];
            s2b += acc[nt][2] * acc[nt][2] + acc[nt][3] * acc[nt][3];
        }
        s1a += __shfl_xor_sync(0xFFFFFFFFu, s1a, 1);
        s2a += __shfl_xor_sync(0xFFFFFFFFu, s2a, 1);
        s1b += __shfl_xor_sync(0xFFFFFFFFu, s1b, 1);
        s2b += __shfl_xor_sync(0xFFFFFFFFu, s2b, 1);
        s1a += __shfl_xor_sync(0xFFFFFFFFu, s1a, 2);
        s2a += __shfl_xor_sync(0xFFFFFFFFu, s2a, 2);
        s1b += __shfl_xor_sync(0xFFFFFFFFu, s1b, 2);
        s2b += __shfl_xor_sync(0xFFFFFFFFu, s2b, 2);
        if ((lane & 3) == 0) {
            int r0 = wm * 16 + (lane >> 2);
            atomicAdd(&sums[r0 * 2 + 0], s1a);
            atomicAdd(&sums[r0 * 2 + 1], s2a);
            atomicAdd(&sums[(r0 + 8) * 2 + 0], s1b);
            atomicAdd(&sums[(r0 + 8) * 2 + 1], s2b);
        }
    }
    __syncthreads();   // barrier 4: sums complete

    // ---- normalize + LeakyReLU + store from registers ----
    {
        int r0 = wm * 16 + (lane >> 2);
        #pragma unroll
        for (int half = 0; half < 2; half++) {
            int r = r0 + half * 8;
            int node = nodeBase + r;
            float mu  = sums[r * 2 + 0] * (1.0f / 128.0f);
            float var = sums[r * 2 + 1] * (1.0f / 128.0f) - mu * mu;
            float rstd = rsqrtf(var + LN_EPS);
            if (node < N) {
                float* orow = out + (size_t)node * O_DIM;
                #pragma unroll
                for (int nt = 0; nt < 8; nt++) {
                    int col = wn * 64 + nt * 8 + 2 * (lane & 3);
                    float v0 = acc[nt][half * 2 + 0];
                    float v1 = acc[nt][half * 2 + 1];
                    float y0 = (v0 - mu) * rstd * sG[col]     + sBe[col];
                    float y1 = (v1 - mu) * rstd * sG[col + 1] + sBe[col + 1];
                    y0 = (y0 >= 0.f) ? y0 : NEG_SLOPE * y0;
                    y1 = (y1 >= 0.f) ? y1 : NEG_SLOPE * y1;
                    *(float2*)(orow + col) = make_float2(y0, y1);
                }
            }
        }
    }
}

extern "C" void kernel_launch(void* const* d_in, const int* in_sizes, int n_in,
                              void* d_out, int out_size)
{
    const float* X     = (const float*)d_in[0];
    const int*   adj   = (const int*)d_in[1];
    const float* W     = (const float*)d_in[2];
    const float* bias  = (const float*)d_in[3];
    const float* gamma = (const float*)d_in[4];
    const float* beta  = (const float*)d_in[5];
    float* out = (float*)d_out;

    int N = in_sizes[0] / F_DIM;
    int n4 = N * (F_DIM / 4);
    int grid = (N + TM - 1) / TM;

    prep_kernel<<<(n4 + 255) / 256, 256>>>(X, W, n4);

    cudaFuncSetAttribute(gnn_mma_kernel,
                         cudaFuncAttributeMaxDynamicSharedMemorySize, SMEM_BYTES);

    cudaLaunchConfig_t cfg = {};
    cfg.gridDim = dim3((unsigned)grid, 1, 1);
    cfg.blockDim = dim3(THREADS, 1, 1);
    cfg.dynamicSmemBytes = SMEM_BYTES;
    cfg.stream = 0;
    cudaLaunchAttribute attrs[1];
    attrs[0].id = cudaLaunchAttributeProgrammaticStreamSerialization;
    attrs[0].val.programmaticStreamSerializationAllowed = 1;
    cfg.attrs = attrs;
    cfg.numAttrs = 1;
    cudaLaunchKernelEx(&cfg, gnn_mma_kernel, X, adj, bias, gamma, beta, out, N);
}

// round 15
// speedup vs baseline: 1.0290x; 1.0290x over previous
#include <cuda_runtime.h>
#include <cuda_fp16.h>
#include <cstdint>

#define THREADS    384
#define TM         96
#define F_DIM      128
#define K_NEIGH    16
#define O_DIM      128
#define KD         256
#define NEG_SLOPE  0.2f
#define LN_EPS     1e-5f
#define X_MAX_ROWS 131072

// smem offsets (bytes)
#define OFF_A      0          // A: 96 rows x 512B (fp16 K=256, XOR-swizzled) = 49152
#define OFF_W      49152      // W chunk: 128 rows x 256B (fp16 K=128, swizzled) = 32768
#define OFF_ADJ    81920      // 96*16 int = 6144
#define OFF_SUMS   88064      // 96 x {s1,s2} f32 = 768
#define OFF_INV    88832      // 96 f32 (+pad)
#define OFF_BIAS   89216      // 128 f32
#define OFF_GAM    89728
#define OFF_BET    90240
#define SMEM_BYTES 90752

__device__ __half g_Wh[O_DIM * KD];
__device__ __half g_Xh[X_MAX_ROWS * F_DIM];

__device__ __forceinline__ uint32_t smem_u32(const void* p) {
    uint32_t a;
    asm("{ .reg .u64 t; cvta.to.shared.u64 t, %1; cvt.u32.u64 %0, t; }" : "=r"(a) : "l"(p));
    return a;
}
__device__ __forceinline__ void ldsm4(uint32_t* r, uint32_t addr) {
    asm volatile("ldmatrix.sync.aligned.m8n8.x4.shared.b16 {%0,%1,%2,%3}, [%4];"
        : "=r"(r[0]), "=r"(r[1]), "=r"(r[2]), "=r"(r[3]) : "r"(addr));
}
__device__ __forceinline__ void mma_f16(float* c, const uint32_t* a, const uint32_t* b) {
    asm volatile("mma.sync.aligned.m16n8k16.row.col.f32.f16.f16.f32 "
        "{%0,%1,%2,%3}, {%4,%5,%6,%7}, {%8,%9}, {%0,%1,%2,%3};"
        : "+f"(c[0]), "+f"(c[1]), "+f"(c[2]), "+f"(c[3])
        : "r"(a[0]), "r"(a[1]), "r"(a[2]), "r"(a[3]), "r"(b[0]), "r"(b[1]));
}
__device__ __forceinline__ uint32_t pkh2(float a, float b) {
    __half2 t = __floats2half2_rn(a, b);
    return *reinterpret_cast<uint32_t*>(&t);
}

// ---------- prep: convert W and X to fp16, then trigger dependent launch ----------
__global__ void prep_kernel(const float* __restrict__ X,
                            const float* __restrict__ W, int n4) {
    int i = blockIdx.x * blockDim.x + threadIdx.x;
    if (i < O_DIM * KD) g_Wh[i] = __float2half_rn(W[i]);
    if (i < n4) {
        float4 v = ((const float4*)X)[i];
        ((uint2*)g_Xh)[i] = make_uint2(pkh2(v.x, v.y), pkh2(v.z, v.w));
    }
    cudaTriggerProgrammaticLaunchCompletion();
}

// ---------- main fused kernel (PDL secondary) ----------
__global__ void __launch_bounds__(THREADS, 2)
gnn_mma_kernel(const int* __restrict__ adj,
               const float* __restrict__ bias,
               const float* __restrict__ gamma,
               const float* __restrict__ beta,
               float* __restrict__ out,
               int N)
{
    extern __shared__ __align__(16) char sp[];
    const uint32_t sbase = smem_u32(sp);

    int*   sAdj = (int*)(sp + OFF_ADJ);
    float* sInv = (float*)(sp + OFF_INV);
    float* sums = (float*)(sp + OFF_SUMS);
    float* sB   = (float*)(sp + OFF_BIAS);
    float* sG   = (float*)(sp + OFF_GAM);
    float* sBe  = (float*)(sp + OFF_BET);

    const int tid  = threadIdx.x;
    const int lane = tid & 31;
    const int warp = tid >> 5;               // 12 warps
    const int wm   = warp >> 1;              // 6 in M (16 rows each)
    const int wn   = warp & 1;               // 2 in N (64 cols each)
    const int nodeBase = blockIdx.x * TM;
    const uint4* Xh4 = (const uint4*)g_Xh;   // 16B groups; 16 per row

    // ======== pre-dependency phase (cheap; does NOT touch g_Wh / g_Xh) ========
    if (tid < 128) { sB[tid] = bias[tid]; sG[tid] = gamma[tid]; sBe[tid] = beta[tid]; }
    if (tid < 192) sums[tid] = 0.f;

    // per-warp: adjacency (8 rows) + ballot count -> inv
    #pragma unroll
    for (int q = 0; q < 4; q++) {
        int idx = q * 32 + lane;                       // 0..127
        int r = warp * 8 + (idx >> 4);
        int node = nodeBase + r;
        int a = -1;
        if (node < N) a = adj[node * K_NEIGH + (idx & 15)];
        sAdj[warp * 128 + idx] = a;
        uint32_t m = __ballot_sync(0xFFFFFFFFu, a >= 0);
        if (lane == 0) {
            int c = __popc(m & 0xFFFFu);
            sInv[warp * 8 + 2 * q] = 1.0f / (float)(c > 1 ? c : 1);
        } else if (lane == 16) {
            int c = __popc(m >> 16);
            sInv[warp * 8 + 2 * q + 1] = 1.0f / (float)(c > 1 ? c : 1);
        }
    }

    // ======== wait for prep's g_Wh / g_Xh ========
    cudaGridDependencySynchronize();

    // stage W chunk 0 (block-stride; latency hides behind gather; barrier 1 covers)
    for (int idx = tid; idx < 2048; idx += THREADS) {
        int o = idx >> 4, u = idx & 15;
        *(uint4*)(sp + OFF_W + o * 256 + (((u) ^ (o & 7)) << 4)) =
            *(const uint4*)(g_Wh + o * KD + u * 8);
    }
    // per-warp: self features -> A cols [0,128): straight fp16 copy from g_Xh
    #pragma unroll
    for (int q = 0; q < 4; q++) {
        int idx = q * 32 + lane;
        int r = warp * 8 + (idx >> 4);
        int u = idx & 15;
        uint4 v = make_uint4(0u, 0u, 0u, 0u);
        int node = nodeBase + r;
        if (node < N) v = Xh4[node * 16 + u];
        *(uint4*)(sp + OFF_A + r * 512 + (((u) ^ (r & 7)) << 4)) = v;
    }
    __syncwarp();

    // per-warp gather: pair-row, half-warp covers one 256B row (4 iterations)
    {
        const int u = lane & 15;
        #pragma unroll 1
        for (int p = 0; p < 4; p++) {
            int r = warp * 8 + 2 * p + (lane >> 4);
            const int* arow = sAdj + r * 16;
            float a0=0.f,a1=0.f,a2=0.f,a3=0.f,a4=0.f,a5=0.f,a6=0.f,a7=0.f;
            #pragma unroll
            for (int k = 0; k < K_NEIGH; k++) {
                int j = arow[k];
                if (j >= 0) {
                    uint4 v = Xh4[j * 16 + u];
                    float2 f;
                    f = __half22float2(*(__half2*)&v.x); a0 += f.x; a1 += f.y;
                    f = __half22float2(*(__half2*)&v.y); a2 += f.x; a3 += f.y;
                    f = __half22float2(*(__half2*)&v.z); a4 += f.x; a5 += f.y;
                    f = __half22float2(*(__half2*)&v.w); a6 += f.x; a7 += f.y;
                }
            }
            float inv = sInv[r];
            uint32_t un = 16u + (uint32_t)u;
            *(uint4*)(sp + OFF_A + r * 512 + ((un ^ (uint32_t)(r & 7)) << 4)) = make_uint4(
                pkh2(a0 * inv, a1 * inv), pkh2(a2 * inv, a3 * inv),
                pkh2(a4 * inv, a5 * inv), pkh2(a6 * inv, a7 * inv));
        }
    }

    float acc[8][4];
    #pragma unroll
    for (int nt = 0; nt < 8; nt++)
        #pragma unroll
        for (int j = 0; j < 4; j++) acc[nt][j] = 0.f;

    const int aRow = wm * 16 + (lane & 15);
    const int aSel = lane >> 4;
    const int bN   = wn * 64 + ((lane >> 4) << 3) + (lane & 7);
    const int bSel = (lane >> 3) & 1;

    __syncthreads();   // barrier 1: A + W0 ready

    #pragma unroll 1
    for (int chunk = 0; chunk < 2; chunk++) {
        if (chunk == 1) {
            for (int idx = tid; idx < 2048; idx += THREADS) {
                int o = idx >> 4, u = idx & 15;
                *(uint4*)(sp + OFF_W + o * 256 + (((u) ^ (o & 7)) << 4)) =
                    *(const uint4*)(g_Wh + o * KD + 128 + u * 8);
            }
            __syncthreads();   // barrier 3: W1 ready
        }
        #pragma unroll
        for (int s = 0; s < 8; s++) {
            uint32_t a[4], bf[16];
            {
                uint32_t ku = (uint32_t)(chunk * 16 + s * 2 + aSel);
                ldsm4(a, sbase + OFF_A + (uint32_t)aRow * 512u
                         + ((ku ^ (uint32_t)(aRow & 7)) << 4));
            }
            #pragma unroll
            for (int q = 0; q < 4; q++) {
                int n = bN + q * 16;
                uint32_t ku = (uint32_t)(s * 2 + bSel);
                ldsm4(bf + q * 4, sbase + OFF_W + (uint32_t)n * 256u
                                  + ((ku ^ (uint32_t)(n & 7)) << 4));
            }
            #pragma unroll
            for (int nt = 0; nt < 8; nt++)
                mma_f16(acc[nt], a, bf + nt * 2);
        }
        if (chunk == 0) __syncthreads();   // barrier 2: GEMM c0 reads done before W restage
    }

    // ---- epilogue: bias + per-row sums (quad shfl + smem atomics) ----
    {
        float s1a = 0.f, s2a = 0.f, s1b = 0.f, s2b = 0.f;
        #pragma unroll
        for (int nt = 0; nt < 8; nt++) {
            int col = wn * 64 + nt * 8 + 2 * (lane & 3);
            float b0 = sB[col], b1 = sB[col + 1];
            acc[nt][0] += b0; acc[nt][1] += b1;
            acc[nt][2] += b0; acc[nt][3] += b1;
            s1a += acc[nt][0] + acc[nt][1];
            s2a += acc[nt][0] * acc[nt][0] + acc[nt][1] * acc[nt][1];
            s1b += acc[nt][2] + acc[nt][3];
            s2b += acc[nt][2] * acc[nt][2] + acc[nt][3] * acc[nt][3];
        }
        s1a += __shfl_xor_sync(0xFFFFFFFFu, s1a, 1);
        s2a += __shfl_xor_sync(0xFFFFFFFFu, s2a, 1);
        s1b += __shfl_xor_sync(0xFFFFFFFFu, s1b, 1);
        s2b += __shfl_xor_sync(0xFFFFFFFFu, s2b, 1);
        s1a += __shfl_xor_sync(0xFFFFFFFFu, s1a, 2);
        s2a += __shfl_xor_sync(0xFFFFFFFFu, s2a, 2);
        s1b += __shfl_xor_sync(0xFFFFFFFFu, s1b, 2);
        s2b += __shfl_xor_sync(0xFFFFFFFFu, s2b, 2);
        if ((lane & 3) == 0) {
            int r0 = wm * 16 + (lane >> 2);
            atomicAdd(&sums[r0 * 2 + 0], s1a);
            atomicAdd(&sums[r0 * 2 + 1], s2a);
            atomicAdd(&sums[(r0 + 8) * 2 + 0], s1b);
            atomicAdd(&sums[(r0 + 8) * 2 + 1], s2b);
        }
    }
    __syncthreads();   // barrier 4: sums complete

    // ---- normalize + LeakyReLU + store from registers ----
    {
        int r0 = wm * 16 + (lane >> 2);
        #pragma unroll
        for (int half = 0; half < 2; half++) {
            int r = r0 + half * 8;
            int node = nodeBase + r;
            float mu  = sums[r * 2 + 0] * (1.0f / 128.0f);
            float var = sums[r * 2 + 1] * (1.0f / 128.0f) - mu * mu;
            float rstd = rsqrtf(var + LN_EPS);
            if (node < N) {
                float* orow = out + (size_t)node * O_DIM;
                #pragma unroll
                for (int nt = 0; nt < 8; nt++) {
                    int col = wn * 64 + nt * 8 + 2 * (lane & 3);
                    float v0 = acc[nt][half * 2 + 0];
                    float v1 = acc[nt][half * 2 + 1];
                    float y0 = (v0 - mu) * rstd * sG[col]     + sBe[col];
                    float y1 = (v1 - mu) * rstd * sG[col + 1] + sBe[col + 1];
                    y0 = (y0 >= 0.f) ? y0 : NEG_SLOPE * y0;
                    y1 = (y1 >= 0.f) ? y1 : NEG_SLOPE * y1;
                    *(float2*)(orow + col) = make_float2(y0, y1);
                }
            }
        }
    }
}

extern "C" void kernel_launch(void* const* d_in, const int* in_sizes, int n_in,
                              void* d_out, int out_size)
{
    const float* X     = (const float*)d_in[0];
    const int*   adj   = (const int*)d_in[1];
    const float* W     = (const float*)d_in[2];
    const float* bias  = (const float*)d_in[3];
    const float* gamma = (const float*)d_in[4];
    const float* beta  = (const float*)d_in[5];
    float* out = (float*)d_out;

    int N = in_sizes[0] / F_DIM;
    int n4 = N * (F_DIM / 4);
    int grid = (N + TM - 1) / TM;

    prep_kernel<<<(n4 + 255) / 256, 256>>>(X, W, n4);

    cudaFuncSetAttribute(gnn_mma_kernel,
                         cudaFuncAttributeMaxDynamicSharedMemorySize, SMEM_BYTES);

    cudaLaunchConfig_t cfg = {};
    cfg.gridDim = dim3((unsigned)grid, 1, 1);
    cfg.blockDim = dim3(THREADS, 1, 1);
    cfg.dynamicSmemBytes = SMEM_BYTES;
    cfg.stream = 0;
    cudaLaunchAttribute attrs[1];
    attrs[0].id = cudaLaunchAttributeProgrammaticStreamSerialization;
    attrs[0].val.programmaticStreamSerializationAllowed = 1;
    cfg.attrs = attrs;
    cfg.numAttrs = 1;
    cudaLaunchKernelEx(&cfg, gnn_mma_kernel, adj, bias, gamma, beta, out, N);
}